// round 1
// baseline (speedup 1.0000x reference)
#include <cuda_runtime.h>

#define B_  2
#define T_  2048
#define DM_ 1024
#define H_  16
#define DH_ 64
#define M_  (B_ * T_)          // 4096 rows for all GEMMs

// ---------------- scratch (device globals; no allocation allowed) ------------
__device__ float g_q[(size_t)B_ * H_ * T_ * DH_];   // (b,h,t,d)
__device__ float g_k[(size_t)B_ * H_ * T_ * DH_];
__device__ float g_v[(size_t)B_ * H_ * T_ * DH_];
__device__ float g_ctx[(size_t)M_ * DM_];           // (b*t, d_model)

// =============================================================================
// SGEMM:  C(M x N) = A(M x K) @ W^T, with W stored row-major (N x K).
// Both operands K-contiguous. 128x128 block tile, K-tile 16, double-buffered,
// 256 threads, 8x8 per-thread fragment.
// QKV=1: A = x, weight picked by blockIdx.z, scatter epilogue into g_q/g_k/g_v.
// QKV=0: A = g_ctx, weight = W0 (Wo), plain epilogue into outp.
// =============================================================================
template <int QKV>
__global__ void __launch_bounds__(256)
sgemm_nt(const float* __restrict__ A,
         const float* __restrict__ W0,
         const float* __restrict__ W1,
         const float* __restrict__ W2,
         float* __restrict__ outp)
{
    __shared__ float As[2][16][128];
    __shared__ float Bs[2][16][128];

    const int tid = threadIdx.x;
    const int m0  = blockIdx.y * 128;
    const int n0  = blockIdx.x * 128;

    const float* Ap;
    const float* Wsel;
    if (QKV) {
        Ap   = A;
        Wsel = (blockIdx.z == 0) ? W0 : ((blockIdx.z == 1) ? W1 : W2);
    } else {
        Ap   = g_ctx;
        Wsel = W0;
    }

    // load mapping: each thread brings 2 float4 of A and 2 float4 of B per K-tile
    const int lr = tid >> 2;          // 0..63
    const int lk = (tid & 3) * 4;     // 0,4,8,12
    const float* aP0 = Ap   + (size_t)(m0 + lr)      * DM_ + lk;
    const float* aP1 = Ap   + (size_t)(m0 + lr + 64) * DM_ + lk;
    const float* bP0 = Wsel + (size_t)(n0 + lr)      * DM_ + lk;
    const float* bP1 = Wsel + (size_t)(n0 + lr + 64) * DM_ + lk;

    const int ty = tid >> 4;          // 0..15 -> rows ty*8
    const int tx = tid & 15;          // 0..15 -> cols tx*8

    float acc[8][8];
#pragma unroll
    for (int i = 0; i < 8; ++i)
#pragma unroll
        for (int j = 0; j < 8; ++j) acc[i][j] = 0.f;

    // prologue: tile 0 into buffer 0
    {
        float4 a0 = *(const float4*)(aP0);
        float4 a1 = *(const float4*)(aP1);
        float4 b0 = *(const float4*)(bP0);
        float4 b1 = *(const float4*)(bP1);
#pragma unroll
        for (int u = 0; u < 4; ++u) {
            As[0][lk + u][lr]      = (&a0.x)[u];
            As[0][lk + u][lr + 64] = (&a1.x)[u];
            Bs[0][lk + u][lr]      = (&b0.x)[u];
            Bs[0][lk + u][lr + 64] = (&b1.x)[u];
        }
    }
    __syncthreads();

    const int NKT = DM_ / 16;   // 64
    for (int kt = 0; kt < NKT; ++kt) {
        const int cb = kt & 1;
        float4 a0n, a1n, b0n, b1n;
        const bool has = (kt + 1) < NKT;
        if (has) {
            const int kk = (kt + 1) * 16;
            a0n = *(const float4*)(aP0 + kk);
            a1n = *(const float4*)(aP1 + kk);
            b0n = *(const float4*)(bP0 + kk);
            b1n = *(const float4*)(bP1 + kk);
        }

#pragma unroll
        for (int k = 0; k < 16; ++k) {
            float af[8], bf[8];
            *(float4*)&af[0] = *(const float4*)&As[cb][k][ty * 8];
            *(float4*)&af[4] = *(const float4*)&As[cb][k][ty * 8 + 4];
            *(float4*)&bf[0] = *(const float4*)&Bs[cb][k][tx * 8];
            *(float4*)&bf[4] = *(const float4*)&Bs[cb][k][tx * 8 + 4];
#pragma unroll
            for (int i = 0; i < 8; ++i)
#pragma unroll
                for (int j = 0; j < 8; ++j)
                    acc[i][j] += af[i] * bf[j];
        }

        if (has) {
            const int nb = cb ^ 1;
#pragma unroll
            for (int u = 0; u < 4; ++u) {
                As[nb][lk + u][lr]      = (&a0n.x)[u];
                As[nb][lk + u][lr + 64] = (&a1n.x)[u];
                Bs[nb][lk + u][lr]      = (&b0n.x)[u];
                Bs[nb][lk + u][lr + 64] = (&b1n.x)[u];
            }
        }
        __syncthreads();
    }

    // ------------------------------ epilogue ---------------------------------
    if (QKV) {
        float* dst = (blockIdx.z == 0) ? g_q : ((blockIdx.z == 1) ? g_k : g_v);
        const int cb0 = n0 + tx * 8;
        const int h   = cb0 >> 6;
        const int d0  = cb0 & 63;
#pragma unroll
        for (int i = 0; i < 8; ++i) {
            const int gm = m0 + ty * 8 + i;
            const int b  = gm >> 11;           // / T_
            const int t  = gm & (T_ - 1);
            float* p = dst + (((size_t)(b * H_ + h) * T_ + t) * DH_ + d0);
            *(float4*)(p)     = make_float4(acc[i][0], acc[i][1], acc[i][2], acc[i][3]);
            *(float4*)(p + 4) = make_float4(acc[i][4], acc[i][5], acc[i][6], acc[i][7]);
        }
    } else {
#pragma unroll
        for (int i = 0; i < 8; ++i) {
            const int gm = m0 + ty * 8 + i;
            float* p = outp + (size_t)gm * DM_ + n0 + tx * 8;
            *(float4*)(p)     = make_float4(acc[i][0], acc[i][1], acc[i][2], acc[i][3]);
            *(float4*)(p + 4) = make_float4(acc[i][4], acc[i][5], acc[i][6], acc[i][7]);
        }
    }
}

// =============================================================================
// Flash attention, fp32, causal. Bq = Bk = 64, 256 threads, 4x4 fragments.
// Online softmax with 16-lane shuffle reductions. P staged via smem for PV.
// grid = (T/64, B*H)
// =============================================================================
#define QPAD 65
#define FLASH_SMEM ((2 * 64 * QPAD + 2 * 64 * 64) * (int)sizeof(float))  // 66048 B

__global__ void __launch_bounds__(256)
flash_kernel()
{
    extern __shared__ float sm[];
    float* Qs = sm;                    // 64 x 65
    float* Ks = Qs + 64 * QPAD;        // 64 x 65
    float* Vs = Ks + 64 * QPAD;        // 64 x 64
    float* Ps = Vs + 64 * 64;          // 64 x 64

    const int tid = threadIdx.x;
    const int qt  = blockIdx.x;
    const int bh  = blockIdx.y;
    const int q0  = qt * 64;

    const float* Qg = g_q + (size_t)bh * T_ * DH_;
    const float* Kg = g_k + (size_t)bh * T_ * DH_;
    const float* Vg = g_v + (size_t)bh * T_ * DH_;

    // load Q tile (64x64): each thread 16 consecutive floats
    {
        const int lr = tid >> 2;
        const int lc = (tid & 3) * 16;
        const float* src = Qg + (size_t)(q0 + lr) * DH_ + lc;
#pragma unroll
        for (int u = 0; u < 4; ++u) {
            float4 v = ((const float4*)src)[u];
            Qs[lr * QPAD + lc + u * 4 + 0] = v.x;
            Qs[lr * QPAD + lc + u * 4 + 1] = v.y;
            Qs[lr * QPAD + lc + u * 4 + 2] = v.z;
            Qs[lr * QPAD + lc + u * 4 + 3] = v.w;
        }
    }

    const int ty = tid >> 4;   // row group, rows ty*4..+3
    const int tx = tid & 15;   // col group, cols tx*4..+3

    float o[4][4];
    float mi[4], li[4];
#pragma unroll
    for (int i = 0; i < 4; ++i) {
        mi[i] = -1e30f; li[i] = 0.f;
#pragma unroll
        for (int j = 0; j < 4; ++j) o[i][j] = 0.f;
    }

    for (int kt = 0; kt <= qt; ++kt) {
        const int k0 = kt * 64;
        __syncthreads();   // previous PV finished before K/V overwrite
        {
            const int lr = tid >> 2;
            const int lc = (tid & 3) * 16;
            const float* ks = Kg + (size_t)(k0 + lr) * DH_ + lc;
            const float* vs = Vg + (size_t)(k0 + lr) * DH_ + lc;
#pragma unroll
            for (int u = 0; u < 4; ++u) {
                float4 kv = ((const float4*)ks)[u];
                Ks[lr * QPAD + lc + u * 4 + 0] = kv.x;
                Ks[lr * QPAD + lc + u * 4 + 1] = kv.y;
                Ks[lr * QPAD + lc + u * 4 + 2] = kv.z;
                Ks[lr * QPAD + lc + u * 4 + 3] = kv.w;
                float4 vv = ((const float4*)vs)[u];
                *(float4*)&Vs[lr * 64 + lc + u * 4] = vv;
            }
        }
        __syncthreads();

        // S = Q @ K^T (64x64), 4x4 fragment per thread
        float s[4][4];
#pragma unroll
        for (int i = 0; i < 4; ++i)
#pragma unroll
            for (int j = 0; j < 4; ++j) s[i][j] = 0.f;

#pragma unroll 8
        for (int d = 0; d < 64; ++d) {
            float qf[4], kf[4];
#pragma unroll
            for (int i = 0; i < 4; ++i) qf[i] = Qs[(ty * 4 + i) * QPAD + d];
#pragma unroll
            for (int j = 0; j < 4; ++j) kf[j] = Ks[(tx * 4 + j) * QPAD + d];
#pragma unroll
            for (int i = 0; i < 4; ++i)
#pragma unroll
                for (int j = 0; j < 4; ++j)
                    s[i][j] += qf[i] * kf[j];
        }

        const float sc = 0.125f;   // 1/sqrt(64)
        if (kt == qt) {
#pragma unroll
            for (int i = 0; i < 4; ++i) {
                const int qg = q0 + ty * 4 + i;
#pragma unroll
                for (int j = 0; j < 4; ++j) {
                    const int kg = k0 + tx * 4 + j;
                    s[i][j] = (kg <= qg) ? s[i][j] * sc : -1e30f;
                }
            }
        } else {
#pragma unroll
            for (int i = 0; i < 4; ++i)
#pragma unroll
                for (int j = 0; j < 4; ++j) s[i][j] *= sc;
        }

        // online softmax (row reductions across the 16 tx lanes)
#pragma unroll
        for (int i = 0; i < 4; ++i) {
            float mx = s[i][0];
#pragma unroll
            for (int j = 1; j < 4; ++j) mx = fmaxf(mx, s[i][j]);
#pragma unroll
            for (int off = 1; off < 16; off <<= 1)
                mx = fmaxf(mx, __shfl_xor_sync(0xffffffffu, mx, off));
            const float mnew  = fmaxf(mi[i], mx);
            const float alpha = __expf(mi[i] - mnew);
            float rs = 0.f;
#pragma unroll
            for (int j = 0; j < 4; ++j) {
                s[i][j] = __expf(s[i][j] - mnew);
                rs += s[i][j];
            }
#pragma unroll
            for (int off = 1; off < 16; off <<= 1)
                rs += __shfl_xor_sync(0xffffffffu, rs, off);
            li[i] = li[i] * alpha + rs;
            mi[i] = mnew;
#pragma unroll
            for (int j = 0; j < 4; ++j) o[i][j] *= alpha;
        }

        // stage P
#pragma unroll
        for (int i = 0; i < 4; ++i)
#pragma unroll
            for (int j = 0; j < 4; ++j)
                Ps[(ty * 4 + i) * 64 + tx * 4 + j] = s[i][j];
        __syncthreads();

        // O += P @ V
#pragma unroll 8
        for (int k = 0; k < 64; ++k) {
            float pf[4], vf[4];
#pragma unroll
            for (int i = 0; i < 4; ++i) pf[i] = Ps[(ty * 4 + i) * 64 + k];
#pragma unroll
            for (int j = 0; j < 4; ++j) vf[j] = Vs[k * 64 + tx * 4 + j];
#pragma unroll
            for (int i = 0; i < 4; ++i)
#pragma unroll
                for (int j = 0; j < 4; ++j)
                    o[i][j] += pf[i] * vf[j];
        }
    }

    // epilogue -> ctx in (b*t, d_model) layout
    const int b = bh / H_;
    const int h = bh % H_;
#pragma unroll
    for (int i = 0; i < 4; ++i) {
        const int trow = q0 + ty * 4 + i;
        const float inv = 1.0f / (li[i] + 1e-9f);
        float4 r = make_float4(o[i][0] * inv, o[i][1] * inv,
                               o[i][2] * inv, o[i][3] * inv);
        *(float4*)&g_ctx[((size_t)(b * T_ + trow)) * DM_ + h * DH_ + tx * 4] = r;
    }
}

// =============================================================================
extern "C" void kernel_launch(void* const* d_in, const int* in_sizes, int n_in,
                              void* d_out, int out_size)
{
    const float* x  = (const float*)d_in[0];
    const float* Wq = (const float*)d_in[1];
    const float* Wk = (const float*)d_in[2];
    const float* Wv = (const float*)d_in[3];
    const float* Wo = (const float*)d_in[4];
    float* out = (float*)d_out;

    cudaFuncSetAttribute(flash_kernel,
                         cudaFuncAttributeMaxDynamicSharedMemorySize, FLASH_SMEM);

    // QKV projections (fused across grid.z)
    dim3 g1(DM_ / 128, M_ / 128, 3);
    sgemm_nt<1><<<g1, 256>>>(x, Wq, Wk, Wv, nullptr);

    // causal flash attention
    dim3 g2(T_ / 64, B_ * H_);
    flash_kernel<<<g2, 256, FLASH_SMEM>>>();

    // output projection
    dim3 g3(DM_ / 128, M_ / 128, 1);
    sgemm_nt<0><<<g3, 256>>>(nullptr, Wo, nullptr, nullptr, out);
}

// round 3
// speedup vs baseline: 3.1642x; 3.1642x over previous
#include <cuda_runtime.h>
#include <cstdint>

#define B_  2
#define T_  2048
#define DM_ 1024
#define H_  16
#define DH_ 64
#define M_  (B_ * T_)          // 4096 rows for all GEMMs

// ---------------- scratch (device globals; no allocation allowed) ------------
__device__ float g_q[(size_t)B_ * H_ * T_ * DH_];   // (b,h,t,d)
__device__ float g_k[(size_t)B_ * H_ * T_ * DH_];
__device__ float g_v[(size_t)B_ * H_ * T_ * DH_];
__device__ float g_ctx[(size_t)M_ * DM_];           // (b*t, d_model)

// ============================ helpers ========================================
__device__ __forceinline__ uint32_t f2tf(float f) {
    uint32_t r;
    asm("cvt.rna.tf32.f32 %0, %1;" : "=r"(r) : "f"(f));
    return r;
}

// D = A(16x8, tf32) * B(8x8, tf32) + D   (fp32 accumulate)
__device__ __forceinline__ void mma8(float* c, const uint32_t* a, const uint32_t* b) {
    asm volatile(
        "mma.sync.aligned.m16n8k8.row.col.f32.tf32.tf32.f32 "
        "{%0,%1,%2,%3}, {%4,%5,%6,%7}, {%8,%9}, {%0,%1,%2,%3};"
        : "+f"(c[0]), "+f"(c[1]), "+f"(c[2]), "+f"(c[3])
        : "r"(a[0]), "r"(a[1]), "r"(a[2]), "r"(a[3]),
          "r"(b[0]), "r"(b[1]));
}

// =============================================================================
// TF32 MMA GEMM: C(M x N) = A(M x 1024) @ W^T  (W row-major N x 1024)
// CTA 128x128, 256 threads (8 warps, 2x4), warp tile 64x32, K-chunk 32,
// register-staged double buffer in smem.
// Smem layout per tile row r (width 32 fp32): addr = r*32 + ((c + 4r) & 31)
// -> all mma fragment loads are bank-conflict-free.
// QKV=1: A = x, W by blockIdx.z, scatter to g_q/g_k/g_v (b,h,t,d).
// QKV=0: A = g_ctx, W = W0, plain row-major store to outp.
// grid = (8, 32, QKV?3:1), block = 256
// =============================================================================
#define GEMM_SMEM (2 * (128 * 32 + 128 * 32) * 4)   // 65536 B

template <int QKV>
__global__ void __launch_bounds__(256, 2)
mma_gemm(const float* __restrict__ A,
         const float* __restrict__ W0,
         const float* __restrict__ W1,
         const float* __restrict__ W2,
         float* __restrict__ outp)
{
    extern __shared__ uint32_t sm[];
    uint32_t* As = sm;           // [2][128*32]
    uint32_t* Bs = sm + 8192;    // [2][128*32]

    const int tid  = threadIdx.x;
    const int lane = tid & 31;
    const int wid  = tid >> 5;
    const int wm   = (wid & 1) * 64;    // warp row base in tile
    const int wn   = (wid >> 1) * 32;   // warp col base in tile
    const int m0   = blockIdx.y * 128;
    const int n0   = blockIdx.x * 128;

    const float* Ap;
    const float* Wsel;
    if (QKV) {
        Ap   = A;
        Wsel = (blockIdx.z == 0) ? W0 : ((blockIdx.z == 1) ? W1 : W2);
    } else {
        Ap   = g_ctx;
        Wsel = W0;
    }

    // global load mapping: 4 float4 of A + 4 float4 of B per thread per K-chunk
    const float* aP[4];
    const float* bP[4];
    int sOf[4];
#pragma unroll
    for (int u = 0; u < 4; ++u) {
        const int f  = tid + 256 * u;
        const int r  = f >> 3;
        const int c4 = (f & 7) * 4;
        aP[u]  = Ap   + (size_t)(m0 + r) * DM_ + c4;
        bP[u]  = Wsel + (size_t)(n0 + r) * DM_ + c4;
        sOf[u] = r * 32 + ((c4 + 4 * r) & 31);
    }

    float acc[4][4][4];
#pragma unroll
    for (int i = 0; i < 4; ++i)
#pragma unroll
        for (int j = 0; j < 4; ++j)
#pragma unroll
            for (int k = 0; k < 4; ++k) acc[i][j][k] = 0.f;

    float4 ra[4], rb[4];

#define G_LOADG(kc) do {                                                  \
        _Pragma("unroll")                                                 \
        for (int u = 0; u < 4; ++u) {                                     \
            ra[u] = *(const float4*)(aP[u] + (kc) * 32);                  \
            rb[u] = *(const float4*)(bP[u] + (kc) * 32);                  \
        }                                                                 \
    } while (0)

#define G_STORE(st) do {                                                  \
        uint32_t* da = As + (st) * 4096;                                  \
        uint32_t* db = Bs + (st) * 4096;                                  \
        _Pragma("unroll")                                                 \
        for (int u = 0; u < 4; ++u) {                                     \
            *(uint4*)&da[sOf[u]] = make_uint4(f2tf(ra[u].x), f2tf(ra[u].y), \
                                              f2tf(ra[u].z), f2tf(ra[u].w)); \
            *(uint4*)&db[sOf[u]] = make_uint4(f2tf(rb[u].x), f2tf(rb[u].y), \
                                              f2tf(rb[u].z), f2tf(rb[u].w)); \
        }                                                                 \
    } while (0)

    G_LOADG(0);
    G_STORE(0);
    __syncthreads();

    for (int kc = 0; kc < 32; ++kc) {
        const int cur = kc & 1;
        const bool has = (kc + 1) < 32;
        if (has) G_LOADG(kc + 1);

        const uint32_t* Sa = As + cur * 4096;
        const uint32_t* Sb = Bs + cur * 4096;
#pragma unroll
        for (int ks = 0; ks < 4; ++ks) {
            const int kk = ks * 8 + (lane & 3);
            uint32_t af[4][4];
#pragma unroll
            for (int mf = 0; mf < 4; ++mf) {
                const int r  = wm + mf * 16 + (lane >> 2);
                const int c0 = (kk + 4 * r) & 31;       // same for r and r+8 (mod 32)
                const int c1 = (kk + 4 + 4 * r) & 31;
                af[mf][0] = Sa[r * 32 + c0];
                af[mf][1] = Sa[(r + 8) * 32 + c0];
                af[mf][2] = Sa[r * 32 + c1];
                af[mf][3] = Sa[(r + 8) * 32 + c1];
            }
#pragma unroll
            for (int nf = 0; nf < 4; ++nf) {
                const int n = wn + nf * 8 + (lane >> 2);
                uint32_t bf[2];
                bf[0] = Sb[n * 32 + ((kk + 4 * n) & 31)];
                bf[1] = Sb[n * 32 + ((kk + 4 + 4 * n) & 31)];
#pragma unroll
                for (int mf = 0; mf < 4; ++mf)
                    mma8(acc[mf][nf], af[mf], bf);
            }
        }

        if (has) G_STORE((kc + 1) & 1);
        __syncthreads();
    }

    // ------------------------------ epilogue ---------------------------------
#pragma unroll
    for (int mf = 0; mf < 4; ++mf) {
        const int row0 = m0 + wm + mf * 16 + (lane >> 2);
        const int row1 = row0 + 8;
#pragma unroll
        for (int nf = 0; nf < 4; ++nf) {
            const int col = n0 + wn + nf * 8 + 2 * (lane & 3);
            if (QKV) {
                float* dst = (blockIdx.z == 0) ? g_q : ((blockIdx.z == 1) ? g_k : g_v);
                const int h  = col >> 6;
                const int d0 = col & 63;
                {
                    const int b = row0 >> 11, t = row0 & (T_ - 1);
                    *(float2*)&dst[(((size_t)(b * H_ + h) * T_ + t) * DH_ + d0)] =
                        make_float2(acc[mf][nf][0], acc[mf][nf][1]);
                }
                {
                    const int b = row1 >> 11, t = row1 & (T_ - 1);
                    *(float2*)&dst[(((size_t)(b * H_ + h) * T_ + t) * DH_ + d0)] =
                        make_float2(acc[mf][nf][2], acc[mf][nf][3]);
                }
            } else {
                *(float2*)&outp[(size_t)row0 * DM_ + col] =
                    make_float2(acc[mf][nf][0], acc[mf][nf][1]);
                *(float2*)&outp[(size_t)row1 * DM_ + col] =
                    make_float2(acc[mf][nf][2], acc[mf][nf][3]);
            }
        }
    }
#undef G_LOADG
#undef G_STORE
}

// =============================================================================
// Flash attention (causal) with tf32 mma. Bq = Bk = 64, 128 threads (4 warps),
// each warp owns a 16-row q slab. S = Q@K^T and O += P@V via m16n8k8.
// Online softmax on the C-fragment layout (2 rows/thread, shfl over 4 lanes).
// P goes through per-warp smem (syncwarp only).
// Smem swizzles (all conflict-free for their access patterns):
//   Q/K/P tiles: addr = r*64 + ((c + 4r) & 63)
//   V tile:      addr = key*64 + ((dh + 8*key) & 63)
// grid = (T/64, B*H), block = 128
// =============================================================================
#define FLASH_SMEM (4 * 64 * 64 * 4)   // Qs,Ks,Vs,Ps = 65536 B

__global__ void __launch_bounds__(128)
flash_mma()
{
    extern __shared__ uint32_t fsm[];
    uint32_t* Qs = fsm;            // 64x64
    uint32_t* Ks = fsm + 4096;
    uint32_t* Vs = fsm + 8192;
    uint32_t* Ps = fsm + 12288;

    const int tid  = threadIdx.x;
    const int lane = tid & 31;
    const int wid  = tid >> 5;
    const int qt   = blockIdx.x;
    const int bh   = blockIdx.y;
    const int q0   = qt * 64;

    const float* Qg = g_q + (size_t)bh * T_ * DH_;
    const float* Kg = g_k + (size_t)bh * T_ * DH_;
    const float* Vg = g_v + (size_t)bh * T_ * DH_;

    // load Q tile (once)
#pragma unroll
    for (int u = 0; u < 8; ++u) {
        const int f  = tid + 128 * u;
        const int r  = f >> 4;
        const int c4 = (f & 15) * 4;
        float4 v = *(const float4*)(Qg + (size_t)(q0 + r) * DH_ + c4);
        *(uint4*)&Qs[r * 64 + ((c4 + 4 * r) & 63)] =
            make_uint4(f2tf(v.x), f2tf(v.y), f2tf(v.z), f2tf(v.w));
    }

    const int rw  = wid * 16 + (lane >> 2);   // q-row (local, row0 of frags)
    const int rw8 = rw + 8;

    float O[8][4];
#pragma unroll
    for (int i = 0; i < 8; ++i)
#pragma unroll
        for (int j = 0; j < 4; ++j) O[i][j] = 0.f;
    float mi[2] = { -1e30f, -1e30f };
    float li[2] = { 0.f, 0.f };

    for (int kt = 0; kt <= qt; ++kt) {
        const int k0 = kt * 64;
        __syncthreads();   // all prior reads of Ks/Vs complete
#pragma unroll
        for (int u = 0; u < 8; ++u) {
            const int f  = tid + 128 * u;
            const int r  = f >> 4;
            const int c4 = (f & 15) * 4;
            float4 kv = *(const float4*)(Kg + (size_t)(k0 + r) * DH_ + c4);
            *(uint4*)&Ks[r * 64 + ((c4 + 4 * r) & 63)] =
                make_uint4(f2tf(kv.x), f2tf(kv.y), f2tf(kv.z), f2tf(kv.w));
            float4 vv = *(const float4*)(Vg + (size_t)(k0 + r) * DH_ + c4);
            *(uint4*)&Vs[r * 64 + ((c4 + 8 * r) & 63)] =
                make_uint4(f2tf(vv.x), f2tf(vv.y), f2tf(vv.z), f2tf(vv.w));
        }
        __syncthreads();

        // ---- S = Q @ K^T ----
        float S[8][4];
#pragma unroll
        for (int i = 0; i < 8; ++i)
#pragma unroll
            for (int j = 0; j < 4; ++j) S[i][j] = 0.f;

#pragma unroll
        for (int ks = 0; ks < 8; ++ks) {
            const int kk = ks * 8 + (lane & 3);
            uint32_t a[4];
            a[0] = Qs[rw  * 64 + ((kk + 4 * rw)  & 63)];
            a[1] = Qs[rw8 * 64 + ((kk + 4 * rw8) & 63)];
            a[2] = Qs[rw  * 64 + ((kk + 4 + 4 * rw)  & 63)];
            a[3] = Qs[rw8 * 64 + ((kk + 4 + 4 * rw8) & 63)];
#pragma unroll
            for (int nf = 0; nf < 8; ++nf) {
                const int n = nf * 8 + (lane >> 2);
                uint32_t b[2];
                b[0] = Ks[n * 64 + ((kk + 4 * n) & 63)];
                b[1] = Ks[n * 64 + ((kk + 4 + 4 * n) & 63)];
                mma8(S[nf], a, b);
            }
        }

        // ---- scale + causal mask + online softmax ----
        const float sc = 0.125f;
        const int   rg0 = q0 + rw;       // global q rows of this thread
        const int   rg1 = q0 + rw8;
        const bool  diag = (kt == qt);

        float mn0 = mi[0], mn1 = mi[1];
#pragma unroll
        for (int nf = 0; nf < 8; ++nf) {
            const int c0 = k0 + nf * 8 + 2 * (lane & 3);
            const int c1 = c0 + 1;
            float s0 = S[nf][0] * sc, s1 = S[nf][1] * sc;
            float s2 = S[nf][2] * sc, s3 = S[nf][3] * sc;
            if (diag) {
                if (c0 > rg0) s0 = -1e30f;
                if (c1 > rg0) s1 = -1e30f;
                if (c0 > rg1) s2 = -1e30f;
                if (c1 > rg1) s3 = -1e30f;
            }
            S[nf][0] = s0; S[nf][1] = s1; S[nf][2] = s2; S[nf][3] = s3;
            mn0 = fmaxf(mn0, fmaxf(s0, s1));
            mn1 = fmaxf(mn1, fmaxf(s2, s3));
        }
        mn0 = fmaxf(mn0, __shfl_xor_sync(0xffffffffu, mn0, 1));
        mn0 = fmaxf(mn0, __shfl_xor_sync(0xffffffffu, mn0, 2));
        mn1 = fmaxf(mn1, __shfl_xor_sync(0xffffffffu, mn1, 1));
        mn1 = fmaxf(mn1, __shfl_xor_sync(0xffffffffu, mn1, 2));

        const float al0 = __expf(mi[0] - mn0);
        const float al1 = __expf(mi[1] - mn1);
        mi[0] = mn0; mi[1] = mn1;

        float rs0 = 0.f, rs1 = 0.f;
#pragma unroll
        for (int nf = 0; nf < 8; ++nf) {
            S[nf][0] = __expf(S[nf][0] - mn0);
            S[nf][1] = __expf(S[nf][1] - mn0);
            S[nf][2] = __expf(S[nf][2] - mn1);
            S[nf][3] = __expf(S[nf][3] - mn1);
            rs0 += S[nf][0] + S[nf][1];
            rs1 += S[nf][2] + S[nf][3];
        }
        rs0 += __shfl_xor_sync(0xffffffffu, rs0, 1);
        rs0 += __shfl_xor_sync(0xffffffffu, rs0, 2);
        rs1 += __shfl_xor_sync(0xffffffffu, rs1, 1);
        rs1 += __shfl_xor_sync(0xffffffffu, rs1, 2);
        li[0] = li[0] * al0 + rs0;
        li[1] = li[1] * al1 + rs1;

#pragma unroll
        for (int nf = 0; nf < 8; ++nf) {
            O[nf][0] *= al0; O[nf][1] *= al0;
            O[nf][2] *= al1; O[nf][3] *= al1;
        }

        // ---- store P to per-warp smem (tf32) ----
#pragma unroll
        for (int nf = 0; nf < 8; ++nf) {
            const int col = nf * 8 + 2 * (lane & 3);
            Ps[rw  * 64 + ((col     + 4 * rw)  & 63)] = f2tf(S[nf][0]);
            Ps[rw  * 64 + ((col + 1 + 4 * rw)  & 63)] = f2tf(S[nf][1]);
            Ps[rw8 * 64 + ((col     + 4 * rw8) & 63)] = f2tf(S[nf][2]);
            Ps[rw8 * 64 + ((col + 1 + 4 * rw8) & 63)] = f2tf(S[nf][3]);
        }
        __syncwarp();

        // ---- O += P @ V ----
#pragma unroll
        for (int ks = 0; ks < 8; ++ks) {
            const int kk = ks * 8 + (lane & 3);   // key index
            uint32_t a[4];
            a[0] = Ps[rw  * 64 + ((kk + 4 * rw)  & 63)];
            a[1] = Ps[rw8 * 64 + ((kk + 4 * rw8) & 63)];
            a[2] = Ps[rw  * 64 + ((kk + 4 + 4 * rw)  & 63)];
            a[3] = Ps[rw8 * 64 + ((kk + 4 + 4 * rw8) & 63)];
#pragma unroll
            for (int nf = 0; nf < 8; ++nf) {
                const int n = nf * 8 + (lane >> 2);   // dh index
                uint32_t b[2];
                b[0] = Vs[kk * 64 + ((n + 8 * kk) & 63)];
                b[1] = Vs[(kk + 4) * 64 + ((n + 8 * (kk + 4)) & 63)];
                mma8(O[nf], a, b);
            }
        }
        __syncwarp();   // P reads done before next iteration's P store
    }

    // ---- epilogue -> g_ctx (b*t, d_model) ----
    const float inv0 = 1.0f / (li[0] + 1e-9f);
    const float inv1 = 1.0f / (li[1] + 1e-9f);
    const int b = bh / H_;
    const int h = bh % H_;
    const int tg0 = q0 + rw;
    const int tg1 = q0 + rw8;
#pragma unroll
    for (int nf = 0; nf < 8; ++nf) {
        const int dh = nf * 8 + 2 * (lane & 3);
        *(float2*)&g_ctx[((size_t)(b * T_ + tg0)) * DM_ + h * DH_ + dh] =
            make_float2(O[nf][0] * inv0, O[nf][1] * inv0);
        *(float2*)&g_ctx[((size_t)(b * T_ + tg1)) * DM_ + h * DH_ + dh] =
            make_float2(O[nf][2] * inv1, O[nf][3] * inv1);
    }
}

// =============================================================================
extern "C" void kernel_launch(void* const* d_in, const int* in_sizes, int n_in,
                              void* d_out, int out_size)
{
    const float* x  = (const float*)d_in[0];
    const float* Wq = (const float*)d_in[1];
    const float* Wk = (const float*)d_in[2];
    const float* Wv = (const float*)d_in[3];
    const float* Wo = (const float*)d_in[4];
    float* out = (float*)d_out;

    cudaFuncSetAttribute(mma_gemm<1>,
                         cudaFuncAttributeMaxDynamicSharedMemorySize, GEMM_SMEM);
    cudaFuncSetAttribute(mma_gemm<0>,
                         cudaFuncAttributeMaxDynamicSharedMemorySize, GEMM_SMEM);
    cudaFuncSetAttribute(flash_mma,
                         cudaFuncAttributeMaxDynamicSharedMemorySize, FLASH_SMEM);

    // QKV projections (fused across grid.z)
    dim3 g1(DM_ / 128, M_ / 128, 3);
    mma_gemm<1><<<g1, 256, GEMM_SMEM>>>(x, Wq, Wk, Wv, nullptr);

    // causal flash attention
    dim3 g2(T_ / 64, B_ * H_);
    flash_mma<<<g2, 128, FLASH_SMEM>>>();

    // output projection
    dim3 g3(DM_ / 128, M_ / 128, 1);
    mma_gemm<0><<<g3, 256, GEMM_SMEM>>>(nullptr, Wo, nullptr, nullptr, out);
}

// round 4
// speedup vs baseline: 3.3964x; 1.0734x over previous
#include <cuda_runtime.h>
#include <cstdint>

#define B_  2
#define T_  2048
#define DM_ 1024
#define H_  16
#define DH_ 64
#define M_  (B_ * T_)          // 4096 rows for all GEMMs

// ---------------- scratch (device globals; no allocation allowed) ------------
__device__ float g_q[(size_t)B_ * H_ * T_ * DH_];   // (b,h,t,d)
__device__ float g_k[(size_t)B_ * H_ * T_ * DH_];
__device__ float g_v[(size_t)B_ * H_ * T_ * DH_];
__device__ float g_ctx[(size_t)M_ * DM_];           // (b*t, d_model)

// ============================ helpers ========================================
__device__ __forceinline__ uint32_t smem_u32(const void* p) {
    uint32_t a;
    asm("{ .reg .u64 t; cvta.to.shared.u64 t, %1; cvt.u32.u64 %0, t; }"
        : "=r"(a) : "l"(p));
    return a;
}

__device__ __forceinline__ uint32_t f2tf(float f) {
    uint32_t r;
    asm("cvt.rna.tf32.f32 %0, %1;" : "=r"(r) : "f"(f));
    return r;
}

// D += A(16x8 tf32) * B(8x8 tf32), fp32 accum
__device__ __forceinline__ void mma8(float* c, const uint32_t* a,
                                     uint32_t b0, uint32_t b1) {
    asm volatile(
        "mma.sync.aligned.m16n8k8.row.col.f32.tf32.tf32.f32 "
        "{%0,%1,%2,%3}, {%4,%5,%6,%7}, {%8,%9}, {%0,%1,%2,%3};"
        : "+f"(c[0]), "+f"(c[1]), "+f"(c[2]), "+f"(c[3])
        : "r"(a[0]), "r"(a[1]), "r"(a[2]), "r"(a[3]), "r"(b0), "r"(b1));
}

__device__ __forceinline__ void ldsm4(uint32_t* d, uint32_t addr) {
    asm volatile("ldmatrix.sync.aligned.m8n8.x4.shared.b16 {%0,%1,%2,%3}, [%4];"
                 : "=r"(d[0]), "=r"(d[1]), "=r"(d[2]), "=r"(d[3]) : "r"(addr));
}

__device__ __forceinline__ void sts128(uint32_t addr, uint32_t x, uint32_t y,
                                       uint32_t z, uint32_t w) {
    asm volatile("st.shared.v4.b32 [%0], {%1,%2,%3,%4};"
                 :: "r"(addr), "r"(x), "r"(y), "r"(z), "r"(w));
}

__device__ __forceinline__ void sts64(uint32_t addr, uint32_t x, uint32_t y) {
    asm volatile("st.shared.v2.b32 [%0], {%1,%2};" :: "r"(addr), "r"(x), "r"(y));
}

// =============================================================================
// TF32 MMA GEMM with ldmatrix: C(M x N) = A(M x 1024) @ W^T (W row-major N x 1024)
// CTA 128x128, 8 warps (2x4), warp tile 64x32, K-chunk 32, double buffered.
// Smem tile row = 32 words (128 B) = 8 16B-blocks; block swizzle: blk ^ (row&7).
// grid = (8, 32, QKV?3:1), block = 256
// =============================================================================
#define GEMM_SMEM (2 * (128 * 32 + 128 * 32) * 4)   // 65536 B

template <int QKV>
__global__ void __launch_bounds__(256, 2)
mma_gemm(const float* __restrict__ A,
         const float* __restrict__ W0,
         const float* __restrict__ W1,
         const float* __restrict__ W2,
         float* __restrict__ outp)
{
    extern __shared__ uint32_t sm[];
    const uint32_t sA = smem_u32(sm);          // [2][128*32] words
    const uint32_t sB = sA + 2 * 16384;        // [2][128*32] words

    const int tid  = threadIdx.x;
    const int lane = tid & 31;
    const int wid  = tid >> 5;
    const int wm   = (wid & 1) * 64;
    const int wn   = (wid >> 1) * 32;
    const int m0   = blockIdx.y * 128;
    const int n0   = blockIdx.x * 128;

    const float* Ap;
    const float* Wsel;
    if (QKV) {
        Ap   = A;
        Wsel = (blockIdx.z == 0) ? W0 : ((blockIdx.z == 1) ? W1 : W2);
    } else {
        Ap   = g_ctx;
        Wsel = W0;
    }

    // global load / smem store mapping (4 float4 of A and B per thread per chunk)
    const float* aP[4];
    const float* bP[4];
    uint32_t sOf[4];
#pragma unroll
    for (int u = 0; u < 4; ++u) {
        const int f  = tid + 256 * u;
        const int r  = f >> 3;
        const int c4 = (f & 7) * 4;
        aP[u]  = Ap   + (size_t)(m0 + r) * DM_ + c4;
        bP[u]  = Wsel + (size_t)(n0 + r) * DM_ + c4;
        sOf[u] = r * 128 + ((((uint32_t)c4 >> 2) ^ (r & 7)) << 4);
    }

    // ldmatrix lane address bases
    const int lr  = lane & 7;
    const int g01 = (lane >> 3) & 1;
    const int g2  = lane >> 4;
    uint32_t arow[4], brow[2];
#pragma unroll
    for (int mf = 0; mf < 4; ++mf) arow[mf] = (wm + mf * 16 + g01 * 8 + lr) * 128;
#pragma unroll
    for (int p = 0; p < 2; ++p)    brow[p]  = (wn + p * 16 + g01 * 8 + lr) * 128;

    float acc[4][4][4];
#pragma unroll
    for (int i = 0; i < 4; ++i)
#pragma unroll
        for (int j = 0; j < 4; ++j)
#pragma unroll
            for (int k = 0; k < 4; ++k) acc[i][j][k] = 0.f;

    float4 ra[4], rb[4];

#define G_LOADG(kc) do {                                                  \
        _Pragma("unroll")                                                 \
        for (int u = 0; u < 4; ++u) {                                     \
            ra[u] = *(const float4*)(aP[u] + (kc) * 32);                  \
            rb[u] = *(const float4*)(bP[u] + (kc) * 32);                  \
        }                                                                 \
    } while (0)

#define G_STORE(st) do {                                                  \
        const uint32_t da = sA + (st) * 16384;                            \
        const uint32_t db = sB + (st) * 16384;                            \
        _Pragma("unroll")                                                 \
        for (int u = 0; u < 4; ++u) {                                     \
            sts128(da + sOf[u], f2tf(ra[u].x), f2tf(ra[u].y),             \
                                 f2tf(ra[u].z), f2tf(ra[u].w));           \
            sts128(db + sOf[u], f2tf(rb[u].x), f2tf(rb[u].y),             \
                                 f2tf(rb[u].z), f2tf(rb[u].w));           \
        }                                                                 \
    } while (0)

    G_LOADG(0);
    G_STORE(0);
    __syncthreads();

    for (int kc = 0; kc < 32; ++kc) {
        const int cur = kc & 1;
        const bool has = (kc + 1) < 32;
        if (has) G_LOADG(kc + 1);

        const uint32_t sa = sA + cur * 16384;
        const uint32_t sb = sB + cur * 16384;
#pragma unroll
        for (int ks = 0; ks < 4; ++ks) {
            const uint32_t blk = (uint32_t)(((2 * ks + g2) ^ lr) << 4);
            uint32_t af[4][4];
#pragma unroll
            for (int mf = 0; mf < 4; ++mf) ldsm4(af[mf], sa + arow[mf] + blk);
#pragma unroll
            for (int p = 0; p < 2; ++p) {
                uint32_t bf[4];
                ldsm4(bf, sb + brow[p] + blk);
#pragma unroll
                for (int mf = 0; mf < 4; ++mf) {
                    mma8(acc[mf][2 * p],     af[mf], bf[0], bf[2]);
                    mma8(acc[mf][2 * p + 1], af[mf], bf[1], bf[3]);
                }
            }
        }

        if (has) G_STORE((kc + 1) & 1);
        __syncthreads();
    }

    // ------------------------------ epilogue ---------------------------------
#pragma unroll
    for (int mf = 0; mf < 4; ++mf) {
        const int row0 = m0 + wm + mf * 16 + (lane >> 2);
        const int row1 = row0 + 8;
#pragma unroll
        for (int nf = 0; nf < 4; ++nf) {
            const int col = n0 + wn + nf * 8 + 2 * (lane & 3);
            if (QKV) {
                float* dst = (blockIdx.z == 0) ? g_q : ((blockIdx.z == 1) ? g_k : g_v);
                const int h  = col >> 6;
                const int d0 = col & 63;
                {
                    const int b = row0 >> 11, t = row0 & (T_ - 1);
                    *(float2*)&dst[(((size_t)(b * H_ + h) * T_ + t) * DH_ + d0)] =
                        make_float2(acc[mf][nf][0], acc[mf][nf][1]);
                }
                {
                    const int b = row1 >> 11, t = row1 & (T_ - 1);
                    *(float2*)&dst[(((size_t)(b * H_ + h) * T_ + t) * DH_ + d0)] =
                        make_float2(acc[mf][nf][2], acc[mf][nf][3]);
                }
            } else {
                *(float2*)&outp[(size_t)row0 * DM_ + col] =
                    make_float2(acc[mf][nf][0], acc[mf][nf][1]);
                *(float2*)&outp[(size_t)row1 * DM_ + col] =
                    make_float2(acc[mf][nf][2], acc[mf][nf][3]);
            }
        }
    }
#undef G_LOADG
#undef G_STORE
}

// =============================================================================
// Flash attention (causal), tf32 mma + ldmatrix. Bq = Bk = 64, 128 threads.
// Q fragments preloaded to registers; Qs smem region reused for P.
// Row = 64 words (256 B) = 16 blocks; Q/K/P swizzle: blk ^ (row&7).
// V swizzle (word): dh ^ ((key&3)<<3)  -> conflict-free B-frag LDS.
// grid = (T/64, B*H), block = 128; qt descending for causal load balance.
// =============================================================================
#define FLASH_SMEM (3 * 64 * 64 * 4)   // Qs/Ps, Ks, Vs = 49152 B

__global__ void __launch_bounds__(128)
flash_mma()
{
    extern __shared__ uint32_t fsm[];
    const uint32_t sQ = smem_u32(fsm);     // 64x64 words; becomes Ps after preload
    const uint32_t sK = sQ + 16384;
    const uint32_t sV = sK + 16384;
    uint32_t* Vw = fsm + 8192;             // word view of Vs

    const int tid  = threadIdx.x;
    const int lane = tid & 31;
    const int wid  = tid >> 5;
    const int qt   = gridDim.x - 1 - blockIdx.x;   // descending work size
    const int bh   = blockIdx.y;
    const int q0   = qt * 64;

    const float* Qg = g_q + (size_t)bh * T_ * DH_;
    const float* Kg = g_k + (size_t)bh * T_ * DH_;
    const float* Vg = g_v + (size_t)bh * T_ * DH_;

    const int lr  = lane & 7;
    const int g01 = (lane >> 3) & 1;
    const int g2  = lane >> 4;

    // ---- load Q tile to smem, then preload warp's fragments ----
#pragma unroll
    for (int u = 0; u < 8; ++u) {
        const int f  = tid + 128 * u;
        const int r  = f >> 4;
        const int c4 = (f & 15) * 4;
        float4 v = *(const float4*)(Qg + (size_t)(q0 + r) * DH_ + c4);
        sts128(sQ + r * 256 + ((((uint32_t)c4 >> 2) ^ (r & 7)) << 4),
               f2tf(v.x), f2tf(v.y), f2tf(v.z), f2tf(v.w));
    }
    __syncthreads();

    const uint32_t qrow = (wid * 16 + g01 * 8 + lr) * 256;
    uint32_t Qf[8][4];
#pragma unroll
    for (int ks = 0; ks < 8; ++ks)
        ldsm4(Qf[ks], sQ + qrow + (uint32_t)(((2 * ks + g2) ^ lr) << 4));

    uint32_t krow[4];
#pragma unroll
    for (int p = 0; p < 4; ++p) krow[p] = (p * 16 + g01 * 8 + lr) * 256;

    const int rw  = wid * 16 + (lane >> 2);
    const int rw8 = rw + 8;

    float O[8][4];
#pragma unroll
    for (int i = 0; i < 8; ++i)
#pragma unroll
        for (int j = 0; j < 4; ++j) O[i][j] = 0.f;
    float mi[2] = { -1e30f, -1e30f };
    float li[2] = { 0.f, 0.f };

    for (int kt = 0; kt <= qt; ++kt) {
        const int k0 = kt * 64;
        __syncthreads();   // prior K/V reads done
#pragma unroll
        for (int u = 0; u < 8; ++u) {
            const int f  = tid + 128 * u;
            const int r  = f >> 4;
            const int c4 = (f & 15) * 4;
            float4 kv = *(const float4*)(Kg + (size_t)(k0 + r) * DH_ + c4);
            sts128(sK + r * 256 + ((((uint32_t)c4 >> 2) ^ (r & 7)) << 4),
                   f2tf(kv.x), f2tf(kv.y), f2tf(kv.z), f2tf(kv.w));
            float4 vv = *(const float4*)(Vg + (size_t)(k0 + r) * DH_ + c4);
            sts128(sV + r * 256 + ((((uint32_t)c4) ^ ((r & 3) << 3)) << 2),
                   f2tf(vv.x), f2tf(vv.y), f2tf(vv.z), f2tf(vv.w));
        }
        __syncthreads();

        // ---- S = Q @ K^T ----
        float S[8][4];
#pragma unroll
        for (int i = 0; i < 8; ++i)
#pragma unroll
            for (int j = 0; j < 4; ++j) S[i][j] = 0.f;

#pragma unroll
        for (int ks = 0; ks < 8; ++ks) {
            const uint32_t blk = (uint32_t)(((2 * ks + g2) ^ lr) << 4);
#pragma unroll
            for (int p = 0; p < 4; ++p) {
                uint32_t bf[4];
                ldsm4(bf, sK + krow[p] + blk);
                mma8(S[2 * p],     Qf[ks], bf[0], bf[2]);
                mma8(S[2 * p + 1], Qf[ks], bf[1], bf[3]);
            }
        }

        // ---- scale + causal mask + online softmax ----
        const float sc  = 0.125f;
        const int   rg0 = q0 + rw;
        const int   rg1 = q0 + rw8;
        const bool  diag = (kt == qt);

        float mn0 = mi[0], mn1 = mi[1];
#pragma unroll
        for (int nf = 0; nf < 8; ++nf) {
            const int c0 = k0 + nf * 8 + 2 * (lane & 3);
            const int c1 = c0 + 1;
            float s0 = S[nf][0] * sc, s1 = S[nf][1] * sc;
            float s2 = S[nf][2] * sc, s3 = S[nf][3] * sc;
            if (diag) {
                if (c0 > rg0) s0 = -1e30f;
                if (c1 > rg0) s1 = -1e30f;
                if (c0 > rg1) s2 = -1e30f;
                if (c1 > rg1) s3 = -1e30f;
            }
            S[nf][0] = s0; S[nf][1] = s1; S[nf][2] = s2; S[nf][3] = s3;
            mn0 = fmaxf(mn0, fmaxf(s0, s1));
            mn1 = fmaxf(mn1, fmaxf(s2, s3));
        }
        mn0 = fmaxf(mn0, __shfl_xor_sync(0xffffffffu, mn0, 1));
        mn0 = fmaxf(mn0, __shfl_xor_sync(0xffffffffu, mn0, 2));
        mn1 = fmaxf(mn1, __shfl_xor_sync(0xffffffffu, mn1, 1));
        mn1 = fmaxf(mn1, __shfl_xor_sync(0xffffffffu, mn1, 2));

        const float al0 = __expf(mi[0] - mn0);
        const float al1 = __expf(mi[1] - mn1);
        mi[0] = mn0; mi[1] = mn1;

        float rs0 = 0.f, rs1 = 0.f;
#pragma unroll
        for (int nf = 0; nf < 8; ++nf) {
            S[nf][0] = __expf(S[nf][0] - mn0);
            S[nf][1] = __expf(S[nf][1] - mn0);
            S[nf][2] = __expf(S[nf][2] - mn1);
            S[nf][3] = __expf(S[nf][3] - mn1);
            rs0 += S[nf][0] + S[nf][1];
            rs1 += S[nf][2] + S[nf][3];
        }
        rs0 += __shfl_xor_sync(0xffffffffu, rs0, 1);
        rs0 += __shfl_xor_sync(0xffffffffu, rs0, 2);
        rs1 += __shfl_xor_sync(0xffffffffu, rs1, 1);
        rs1 += __shfl_xor_sync(0xffffffffu, rs1, 2);
        li[0] = li[0] * al0 + rs0;
        li[1] = li[1] * al1 + rs1;

#pragma unroll
        for (int nf = 0; nf < 8; ++nf) {
            O[nf][0] *= al0; O[nf][1] *= al0;
            O[nf][2] *= al1; O[nf][3] *= al1;
        }

        // ---- store P (tf32) into Qs-region smem, warp-private rows ----
#pragma unroll
        for (int nf = 0; nf < 8; ++nf) {
            const int col = nf * 8 + 2 * (lane & 3);   // even
            const uint32_t boff = ((((uint32_t)col >> 2) ^ (rw & 7)) << 4) +
                                  (col & 3) * 4;
            sts64(sQ + rw * 256 + boff, f2tf(S[nf][0]), f2tf(S[nf][1]));
            const uint32_t boff8 = ((((uint32_t)col >> 2) ^ (rw8 & 7)) << 4) +
                                   (col & 3) * 4;
            sts64(sQ + rw8 * 256 + boff8, f2tf(S[nf][2]), f2tf(S[nf][3]));
        }
        __syncwarp();

        // ---- O += P @ V ----
        const int kq = lane & 3;           // k' within octet
        const int rr = lane >> 2;          // dh low bits
#pragma unroll
        for (int ks = 0; ks < 8; ++ks) {
            uint32_t pa[4];
            ldsm4(pa, sQ + qrow + (uint32_t)(((2 * ks + g2) ^ lr) << 4));
            const int kk = ks * 8 + kq;
            const int vbase = kk * 64 + rr;
#pragma unroll
            for (int nf = 0; nf < 8; ++nf) {
                const int vc = vbase + ((nf ^ kq) << 3);
                mma8(O[nf], pa, Vw[vc], Vw[vc + 4 * 64]);
            }
        }
        __syncwarp();   // P reads done before next kt's P store
    }

    // ---- epilogue -> g_ctx (b*t, d_model) ----
    const float inv0 = 1.0f / (li[0] + 1e-9f);
    const float inv1 = 1.0f / (li[1] + 1e-9f);
    const int b = bh / H_;
    const int h = bh % H_;
    const int tg0 = q0 + rw;
    const int tg1 = q0 + rw8;
#pragma unroll
    for (int nf = 0; nf < 8; ++nf) {
        const int dh = nf * 8 + 2 * (lane & 3);
        *(float2*)&g_ctx[((size_t)(b * T_ + tg0)) * DM_ + h * DH_ + dh] =
            make_float2(O[nf][0] * inv0, O[nf][1] * inv0);
        *(float2*)&g_ctx[((size_t)(b * T_ + tg1)) * DM_ + h * DH_ + dh] =
            make_float2(O[nf][2] * inv1, O[nf][3] * inv1);
    }
}

// =============================================================================
extern "C" void kernel_launch(void* const* d_in, const int* in_sizes, int n_in,
                              void* d_out, int out_size)
{
    const float* x  = (const float*)d_in[0];
    const float* Wq = (const float*)d_in[1];
    const float* Wk = (const float*)d_in[2];
    const float* Wv = (const float*)d_in[3];
    const float* Wo = (const float*)d_in[4];
    float* out = (float*)d_out;

    cudaFuncSetAttribute(mma_gemm<1>,
                         cudaFuncAttributeMaxDynamicSharedMemorySize, GEMM_SMEM);
    cudaFuncSetAttribute(mma_gemm<0>,
                         cudaFuncAttributeMaxDynamicSharedMemorySize, GEMM_SMEM);
    cudaFuncSetAttribute(flash_mma,
                         cudaFuncAttributeMaxDynamicSharedMemorySize, FLASH_SMEM);

    // QKV projections (fused across grid.z)
    dim3 g1(DM_ / 128, M_ / 128, 3);
    mma_gemm<1><<<g1, 256, GEMM_SMEM>>>(x, Wq, Wk, Wv, nullptr);

    // causal flash attention
    dim3 g2(T_ / 64, B_ * H_);
    flash_mma<<<g2, 128, FLASH_SMEM>>>();

    // output projection
    dim3 g3(DM_ / 128, M_ / 128, 1);
    mma_gemm<0><<<g3, 256, GEMM_SMEM>>>(nullptr, Wo, nullptr, nullptr, out);
}

// round 5
// speedup vs baseline: 3.9234x; 1.1552x over previous
#include <cuda_runtime.h>
#include <cstdint>

#define B_  2
#define T_  2048
#define DM_ 1024
#define H_  16
#define DH_ 64
#define M_  (B_ * T_)          // 4096 rows for all GEMMs

// ---------------- scratch (device globals; no allocation allowed) ------------
__device__ float g_q[(size_t)B_ * H_ * T_ * DH_];   // (b,h,t,d) tf32-rounded
__device__ float g_k[(size_t)B_ * H_ * T_ * DH_];
__device__ float g_v[(size_t)B_ * H_ * T_ * DH_];
__device__ float g_ctx[(size_t)M_ * DM_];           // (b*t, d_model) tf32-rounded
__device__ float g_x [(size_t)M_ * DM_];            // tf32-rounded x
__device__ float g_wq[(size_t)DM_ * DM_];
__device__ float g_wk[(size_t)DM_ * DM_];
__device__ float g_wv[(size_t)DM_ * DM_];
__device__ float g_wo[(size_t)DM_ * DM_];

// ============================ helpers ========================================
__device__ __forceinline__ uint32_t smem_u32(const void* p) {
    uint32_t a;
    asm("{ .reg .u64 t; cvta.to.shared.u64 t, %1; cvt.u32.u64 %0, t; }"
        : "=r"(a) : "l"(p));
    return a;
}

__device__ __forceinline__ uint32_t f2tf(float f) {
    uint32_t r;
    asm("cvt.rna.tf32.f32 %0, %1;" : "=r"(r) : "f"(f));
    return r;
}

// D += A(16x8 tf32) * B(8x8 tf32), fp32 accum
__device__ __forceinline__ void mma8(float* c, const uint32_t* a,
                                     uint32_t b0, uint32_t b1) {
    asm volatile(
        "mma.sync.aligned.m16n8k8.row.col.f32.tf32.tf32.f32 "
        "{%0,%1,%2,%3}, {%4,%5,%6,%7}, {%8,%9}, {%0,%1,%2,%3};"
        : "+f"(c[0]), "+f"(c[1]), "+f"(c[2]), "+f"(c[3])
        : "r"(a[0]), "r"(a[1]), "r"(a[2]), "r"(a[3]), "r"(b0), "r"(b1));
}

__device__ __forceinline__ void ldsm4(uint32_t* d, uint32_t addr) {
    asm volatile("ldmatrix.sync.aligned.m8n8.x4.shared.b16 {%0,%1,%2,%3}, [%4];"
                 : "=r"(d[0]), "=r"(d[1]), "=r"(d[2]), "=r"(d[3]) : "r"(addr));
}

__device__ __forceinline__ void sts64(uint32_t addr, uint32_t x, uint32_t y) {
    asm volatile("st.shared.v2.b32 [%0], {%1,%2};" :: "r"(addr), "r"(x), "r"(y));
}

__device__ __forceinline__ void cpa16(uint32_t dst, const float* src) {
    asm volatile("cp.async.cg.shared.global [%0], [%1], 16;"
                 :: "r"(dst), "l"(src) : "memory");
}
#define CP_COMMIT() asm volatile("cp.async.commit_group;" ::: "memory")
#define CP_WAIT0()  asm volatile("cp.async.wait_group 0;" ::: "memory")
#define CP_WAIT1()  asm volatile("cp.async.wait_group 1;" ::: "memory")

// =============================================================================
// Pre-convert x and the 4 weights to tf32-rounded fp32 copies.
// float4 regions: x 1048576 | wq 262144 | wk 262144 | wv 262144 | wo 262144
// =============================================================================
#define NX4 1048576
#define NW4 262144
#define CONV_TOTAL (NX4 + 4 * NW4)

__global__ void __launch_bounds__(256)
conv_tf32(const float* __restrict__ x,  const float* __restrict__ wq,
          const float* __restrict__ wk, const float* __restrict__ wv,
          const float* __restrict__ wo)
{
    const int i = blockIdx.x * 256 + threadIdx.x;
    if (i >= CONV_TOTAL) return;
    const float4* src; float4* dst; int j;
    if (i < NX4)               { src = (const float4*)x;  dst = (float4*)g_x;  j = i; }
    else if (i < NX4 + NW4)    { src = (const float4*)wq; dst = (float4*)g_wq; j = i - NX4; }
    else if (i < NX4 + 2*NW4)  { src = (const float4*)wk; dst = (float4*)g_wk; j = i - NX4 - NW4; }
    else if (i < NX4 + 3*NW4)  { src = (const float4*)wv; dst = (float4*)g_wv; j = i - NX4 - 2*NW4; }
    else                       { src = (const float4*)wo; dst = (float4*)g_wo; j = i - NX4 - 3*NW4; }
    float4 v = src[j];
    dst[j] = make_float4(__uint_as_float(f2tf(v.x)), __uint_as_float(f2tf(v.y)),
                         __uint_as_float(f2tf(v.z)), __uint_as_float(f2tf(v.w)));
}

// =============================================================================
// TF32 MMA GEMM, cp.async 3-stage pipeline.
// C(M x N) = A(M x 1024) @ W^T (W row-major N x 1024), operands pre-rounded.
// CTA 128x128, 8 warps (2x4), warp tile 64x32, K-chunk 32.
// Smem row = 32 words (128 B) = 8 16B-blocks; swizzle blk ^ (row&7).
// grid = (8, 32, QKV?3:1), block = 256
// =============================================================================
#define ST 3
#define GEMM_SMEM (ST * 2 * 128 * 32 * 4)   // 98304 B

template <int QKV>
__global__ void __launch_bounds__(256, 2)
mma_gemm(float* __restrict__ outp)
{
    extern __shared__ uint32_t sm[];
    const uint32_t sA = smem_u32(sm);          // ST stages x 16KB
    const uint32_t sB = sA + ST * 16384;

    const int tid  = threadIdx.x;
    const int lane = tid & 31;
    const int wid  = tid >> 5;
    const int wm   = (wid & 1) * 64;
    const int wn   = (wid >> 1) * 32;
    const int m0   = blockIdx.y * 128;
    const int n0   = blockIdx.x * 128;

    const float* Ap   = QKV ? g_x : g_ctx;
    const float* Wsel = QKV ? ((blockIdx.z == 0) ? g_wq :
                               (blockIdx.z == 1) ? g_wk : g_wv)
                            : g_wo;

    const float* aSrc[4];
    const float* bSrc[4];
    uint32_t sOf[4];
#pragma unroll
    for (int u = 0; u < 4; ++u) {
        const int f  = tid + 256 * u;
        const int r  = f >> 3;
        const int c4 = (f & 7) * 4;
        aSrc[u] = Ap   + (size_t)(m0 + r) * DM_ + c4;
        bSrc[u] = Wsel + (size_t)(n0 + r) * DM_ + c4;
        sOf[u]  = r * 128 + ((((uint32_t)c4 >> 2) ^ (r & 7)) << 4);
    }

    // ldmatrix lane address bases
    const int lr  = lane & 7;
    const int g01 = (lane >> 3) & 1;
    const int g2  = lane >> 4;
    uint32_t arow[4], brow[2];
#pragma unroll
    for (int mf = 0; mf < 4; ++mf) arow[mf] = (wm + mf * 16 + g01 * 8 + lr) * 128;
#pragma unroll
    for (int p = 0; p < 2; ++p)    brow[p]  = (wn + p * 16 + g01 * 8 + lr) * 128;

    float acc[4][4][4];
#pragma unroll
    for (int i = 0; i < 4; ++i)
#pragma unroll
        for (int j = 0; j < 4; ++j)
#pragma unroll
            for (int k = 0; k < 4; ++k) acc[i][j][k] = 0.f;

#define G_ISSUE(kc) do {                                                  \
        const uint32_t da = sA + ((kc) % ST) * 16384;                     \
        const uint32_t db = sB + ((kc) % ST) * 16384;                     \
        _Pragma("unroll")                                                 \
        for (int u = 0; u < 4; ++u) {                                     \
            cpa16(da + sOf[u], aSrc[u] + (kc) * 32);                      \
            cpa16(db + sOf[u], bSrc[u] + (kc) * 32);                      \
        }                                                                 \
        CP_COMMIT();                                                      \
    } while (0)

    G_ISSUE(0);
    G_ISSUE(1);

    for (int kc = 0; kc < 32; ++kc) {
        if (kc < 31) CP_WAIT1(); else CP_WAIT0();
        __syncthreads();
        if (kc + 2 < 32) G_ISSUE(kc + 2);

        const uint32_t sa = sA + (kc % ST) * 16384;
        const uint32_t sb = sB + (kc % ST) * 16384;
#pragma unroll
        for (int ks = 0; ks < 4; ++ks) {
            const uint32_t blk = (uint32_t)(((2 * ks + g2) ^ lr) << 4);
            uint32_t af[4][4];
#pragma unroll
            for (int mf = 0; mf < 4; ++mf) ldsm4(af[mf], sa + arow[mf] + blk);
#pragma unroll
            for (int p = 0; p < 2; ++p) {
                uint32_t bf[4];
                ldsm4(bf, sb + brow[p] + blk);
#pragma unroll
                for (int mf = 0; mf < 4; ++mf) {
                    mma8(acc[mf][2 * p],     af[mf], bf[0], bf[2]);
                    mma8(acc[mf][2 * p + 1], af[mf], bf[1], bf[3]);
                }
            }
        }
        __syncthreads();   // all warps done with this stage before it is refilled
    }

    // ------------------------------ epilogue ---------------------------------
#pragma unroll
    for (int mf = 0; mf < 4; ++mf) {
        const int row0 = m0 + wm + mf * 16 + (lane >> 2);
        const int row1 = row0 + 8;
#pragma unroll
        for (int nf = 0; nf < 4; ++nf) {
            const int col = n0 + wn + nf * 8 + 2 * (lane & 3);
            if (QKV) {
                // store tf32-rounded so flash can consume without converting
                float* dst = (blockIdx.z == 0) ? g_q : ((blockIdx.z == 1) ? g_k : g_v);
                const int h  = col >> 6;
                const int d0 = col & 63;
                {
                    const int b = row0 >> 11, t = row0 & (T_ - 1);
                    *(uint2*)&dst[(((size_t)(b * H_ + h) * T_ + t) * DH_ + d0)] =
                        make_uint2(f2tf(acc[mf][nf][0]), f2tf(acc[mf][nf][1]));
                }
                {
                    const int b = row1 >> 11, t = row1 & (T_ - 1);
                    *(uint2*)&dst[(((size_t)(b * H_ + h) * T_ + t) * DH_ + d0)] =
                        make_uint2(f2tf(acc[mf][nf][2]), f2tf(acc[mf][nf][3]));
                }
            } else {
                *(float2*)&outp[(size_t)row0 * DM_ + col] =
                    make_float2(acc[mf][nf][0], acc[mf][nf][1]);
                *(float2*)&outp[(size_t)row1 * DM_ + col] =
                    make_float2(acc[mf][nf][2], acc[mf][nf][3]);
            }
        }
    }
#undef G_ISSUE
}

// =============================================================================
// Flash attention (causal), tf32 mma + ldmatrix + double-buffered cp.async K/V.
// Bq = Bk = 64, 128 threads. Q fragments in registers; Q smem reused for P.
// Q/K/P swizzle: 16B blk ^ (row&7).  V swizzle (word): dh ^ ((key&3)<<3).
// Smem: Q/P 16KB | K x2 32KB | V x2 32KB = 80KB.
// grid = (T/64, B*H); qt descending for causal load balance.
// =============================================================================
#define FLASH_SMEM ((4096 + 8192 + 8192) * 4)   // 81920 B

__global__ void __launch_bounds__(128)
flash_mma()
{
    extern __shared__ uint32_t fsm[];
    const uint32_t sQ = smem_u32(fsm);         // 4096 words (Q, then P)
    const uint32_t sK = sQ + 16384;            // 2 x 4096 words
    const uint32_t sV = sQ + 49152;            // 2 x 4096 words
    uint32_t* Vw = fsm + 12288;                // word view of V region

    const int tid  = threadIdx.x;
    const int lane = tid & 31;
    const int wid  = tid >> 5;
    const int qt   = gridDim.x - 1 - blockIdx.x;
    const int bh   = blockIdx.y;
    const int q0   = qt * 64;

    const float* Qg = g_q + (size_t)bh * T_ * DH_;
    const float* Kg = g_k + (size_t)bh * T_ * DH_;
    const float* Vg = g_v + (size_t)bh * T_ * DH_;

    const int lr  = lane & 7;
    const int g01 = (lane >> 3) & 1;
    const int g2  = lane >> 4;

    // per-thread copy mapping (8 x 16B each for K and V per tile; same for Q)
    int cr[8], cc4[8];
    uint32_t kOf[8], vOf[8];
#pragma unroll
    for (int u = 0; u < 8; ++u) {
        const int f  = tid + 128 * u;
        cr[u]  = f >> 4;
        cc4[u] = (f & 15) * 4;
        kOf[u] = cr[u] * 256 + ((((uint32_t)cc4[u] >> 2) ^ (cr[u] & 7)) << 4);
        vOf[u] = cr[u] * 256 + ((((uint32_t)cc4[u]) ^ ((cr[u] & 3) << 3)) << 2);
    }

    // ---- Q tile via cp.async (group 1), then K/V tile 0 (group 2) ----
#pragma unroll
    for (int u = 0; u < 8; ++u)
        cpa16(sQ + kOf[u], Qg + (size_t)(q0 + cr[u]) * DH_ + cc4[u]);
    CP_COMMIT();

#define KV_ISSUE(kt) do {                                                    \
        const uint32_t kb = sK + ((kt) & 1) * 16384;                         \
        const uint32_t vb = sV + ((kt) & 1) * 16384;                         \
        const int _k0 = (kt) * 64;                                           \
        _Pragma("unroll")                                                    \
        for (int u = 0; u < 8; ++u) {                                        \
            cpa16(kb + kOf[u], Kg + (size_t)(_k0 + cr[u]) * DH_ + cc4[u]);   \
            cpa16(vb + vOf[u], Vg + (size_t)(_k0 + cr[u]) * DH_ + cc4[u]);   \
        }                                                                    \
        CP_COMMIT();                                                         \
    } while (0)

    KV_ISSUE(0);

    CP_WAIT1();          // Q ready (K/V 0 may still be in flight)
    __syncthreads();

    const uint32_t qrow = (wid * 16 + g01 * 8 + lr) * 256;
    uint32_t Qf[8][4];
#pragma unroll
    for (int ks = 0; ks < 8; ++ks)
        ldsm4(Qf[ks], sQ + qrow + (uint32_t)(((2 * ks + g2) ^ lr) << 4));

    uint32_t krow[4];
#pragma unroll
    for (int p = 0; p < 4; ++p) krow[p] = (p * 16 + g01 * 8 + lr) * 256;

    const int rw  = wid * 16 + (lane >> 2);
    const int rw8 = rw + 8;

    float O[8][4];
#pragma unroll
    for (int i = 0; i < 8; ++i)
#pragma unroll
        for (int j = 0; j < 4; ++j) O[i][j] = 0.f;
    float mi[2] = { -1e30f, -1e30f };
    float li[2] = { 0.f, 0.f };

    for (int kt = 0; kt <= qt; ++kt) {
        const int k0 = kt * 64;
        CP_WAIT0();          // K/V for kt landed
        __syncthreads();     // visible to all; prior reads of other buffer done
        if (kt < qt) KV_ISSUE(kt + 1);   // overlap next copy with this compute

        const uint32_t kb = sK + (kt & 1) * 16384;
        const int      vs = (kt & 1) * 4096;    // word offset into Vw

        // ---- S = Q @ K^T ----
        float S[8][4];
#pragma unroll
        for (int i = 0; i < 8; ++i)
#pragma unroll
            for (int j = 0; j < 4; ++j) S[i][j] = 0.f;

#pragma unroll
        for (int ks = 0; ks < 8; ++ks) {
            const uint32_t blk = (uint32_t)(((2 * ks + g2) ^ lr) << 4);
#pragma unroll
            for (int p = 0; p < 4; ++p) {
                uint32_t bf[4];
                ldsm4(bf, kb + krow[p] + blk);
                mma8(S[2 * p],     Qf[ks], bf[0], bf[2]);
                mma8(S[2 * p + 1], Qf[ks], bf[1], bf[3]);
            }
        }

        // ---- scale + causal mask + online softmax ----
        const float sc  = 0.125f;
        const int   rg0 = q0 + rw;
        const int   rg1 = q0 + rw8;
        const bool  diag = (kt == qt);

        float mn0 = mi[0], mn1 = mi[1];
#pragma unroll
        for (int nf = 0; nf < 8; ++nf) {
            const int c0 = k0 + nf * 8 + 2 * (lane & 3);
            const int c1 = c0 + 1;
            float s0 = S[nf][0] * sc, s1 = S[nf][1] * sc;
            float s2 = S[nf][2] * sc, s3 = S[nf][3] * sc;
            if (diag) {
                if (c0 > rg0) s0 = -1e30f;
                if (c1 > rg0) s1 = -1e30f;
                if (c0 > rg1) s2 = -1e30f;
                if (c1 > rg1) s3 = -1e30f;
            }
            S[nf][0] = s0; S[nf][1] = s1; S[nf][2] = s2; S[nf][3] = s3;
            mn0 = fmaxf(mn0, fmaxf(s0, s1));
            mn1 = fmaxf(mn1, fmaxf(s2, s3));
        }
        mn0 = fmaxf(mn0, __shfl_xor_sync(0xffffffffu, mn0, 1));
        mn0 = fmaxf(mn0, __shfl_xor_sync(0xffffffffu, mn0, 2));
        mn1 = fmaxf(mn1, __shfl_xor_sync(0xffffffffu, mn1, 1));
        mn1 = fmaxf(mn1, __shfl_xor_sync(0xffffffffu, mn1, 2));

        const float al0 = __expf(mi[0] - mn0);
        const float al1 = __expf(mi[1] - mn1);
        mi[0] = mn0; mi[1] = mn1;

        float rs0 = 0.f, rs1 = 0.f;
#pragma unroll
        for (int nf = 0; nf < 8; ++nf) {
            S[nf][0] = __expf(S[nf][0] - mn0);
            S[nf][1] = __expf(S[nf][1] - mn0);
            S[nf][2] = __expf(S[nf][2] - mn1);
            S[nf][3] = __expf(S[nf][3] - mn1);
            rs0 += S[nf][0] + S[nf][1];
            rs1 += S[nf][2] + S[nf][3];
        }
        rs0 += __shfl_xor_sync(0xffffffffu, rs0, 1);
        rs0 += __shfl_xor_sync(0xffffffffu, rs0, 2);
        rs1 += __shfl_xor_sync(0xffffffffu, rs1, 1);
        rs1 += __shfl_xor_sync(0xffffffffu, rs1, 2);
        li[0] = li[0] * al0 + rs0;
        li[1] = li[1] * al1 + rs1;

#pragma unroll
        for (int nf = 0; nf < 8; ++nf) {
            O[nf][0] *= al0; O[nf][1] *= al0;
            O[nf][2] *= al1; O[nf][3] *= al1;
        }

        // ---- store P (tf32) into Q-region smem, warp-private rows ----
#pragma unroll
        for (int nf = 0; nf < 8; ++nf) {
            const int col = nf * 8 + 2 * (lane & 3);
            const uint32_t boff = ((((uint32_t)col >> 2) ^ (rw & 7)) << 4) +
                                  (col & 3) * 4;
            sts64(sQ + rw * 256 + boff, f2tf(S[nf][0]), f2tf(S[nf][1]));
            const uint32_t boff8 = ((((uint32_t)col >> 2) ^ (rw8 & 7)) << 4) +
                                   (col & 3) * 4;
            sts64(sQ + rw8 * 256 + boff8, f2tf(S[nf][2]), f2tf(S[nf][3]));
        }
        __syncwarp();

        // ---- O += P @ V ----
        const int kq = lane & 3;
        const int rr = lane >> 2;
#pragma unroll
        for (int ks = 0; ks < 8; ++ks) {
            uint32_t pa[4];
            ldsm4(pa, sQ + qrow + (uint32_t)(((2 * ks + g2) ^ lr) << 4));
            const int kk = ks * 8 + kq;
            const int vbase = vs + kk * 64 + rr;
#pragma unroll
            for (int nf = 0; nf < 8; ++nf) {
                const int vc = vbase + ((nf ^ kq) << 3);
                mma8(O[nf], pa, Vw[vc], Vw[vc + 4 * 64]);
            }
        }
        __syncwarp();
    }

    // ---- epilogue -> g_ctx, tf32-rounded for the Wo GEMM ----
    const float inv0 = 1.0f / (li[0] + 1e-9f);
    const float inv1 = 1.0f / (li[1] + 1e-9f);
    const int b = bh / H_;
    const int h = bh % H_;
    const int tg0 = q0 + rw;
    const int tg1 = q0 + rw8;
#pragma unroll
    for (int nf = 0; nf < 8; ++nf) {
        const int dh = nf * 8 + 2 * (lane & 3);
        *(uint2*)&g_ctx[((size_t)(b * T_ + tg0)) * DM_ + h * DH_ + dh] =
            make_uint2(f2tf(O[nf][0] * inv0), f2tf(O[nf][1] * inv0));
        *(uint2*)&g_ctx[((size_t)(b * T_ + tg1)) * DM_ + h * DH_ + dh] =
            make_uint2(f2tf(O[nf][2] * inv1), f2tf(O[nf][3] * inv1));
    }
#undef KV_ISSUE
}

// =============================================================================
extern "C" void kernel_launch(void* const* d_in, const int* in_sizes, int n_in,
                              void* d_out, int out_size)
{
    const float* x  = (const float*)d_in[0];
    const float* Wq = (const float*)d_in[1];
    const float* Wk = (const float*)d_in[2];
    const float* Wv = (const float*)d_in[3];
    const float* Wo = (const float*)d_in[4];
    float* out = (float*)d_out;

    cudaFuncSetAttribute(mma_gemm<1>,
                         cudaFuncAttributeMaxDynamicSharedMemorySize, GEMM_SMEM);
    cudaFuncSetAttribute(mma_gemm<0>,
                         cudaFuncAttributeMaxDynamicSharedMemorySize, GEMM_SMEM);
    cudaFuncSetAttribute(flash_mma,
                         cudaFuncAttributeMaxDynamicSharedMemorySize, FLASH_SMEM);

    // 0) pre-round operands to tf32
    conv_tf32<<<(CONV_TOTAL + 255) / 256, 256>>>(x, Wq, Wk, Wv, Wo);

    // 1) QKV projections (fused across grid.z)
    dim3 g1(DM_ / 128, M_ / 128, 3);
    mma_gemm<1><<<g1, 256, GEMM_SMEM>>>(nullptr);

    // 2) causal flash attention
    dim3 g2(T_ / 64, B_ * H_);
    flash_mma<<<g2, 128, FLASH_SMEM>>>();

    // 3) output projection
    dim3 g3(DM_ / 128, M_ / 128, 1);
    mma_gemm<0><<<g3, 256, GEMM_SMEM>>>(out);
}